// round 16
// baseline (speedup 1.0000x reference)
#include <cuda_runtime.h>
#include <cuda_bf16.h>

#define K_F 16
#define T_TYPES 4
#define OUT_W (K_F * T_TYPES)
#define PI_F 3.14159265358979323846f
#define LOG2E_F 1.44269504088896340736f
#define BLK 256
#define NBLK_TARGET 888                 // 6 blocks/SM * 148
#define PACK2_CAP_WORDS 12288           // 48KB -> V <= 196608
#define TYPE_CAP (1 << 20)

// 2-bit type table: 16 nodes/word (valid only when g_unmatched == 0)
__device__ unsigned int g_pack2[PACK2_CAP_WORDS];
// byte table fallback (type or -1), always built when V <= TYPE_CAP
__device__ signed char g_type[TYPE_CAP];
__device__ int g_unmatched;

// Launch 1: zero output, reset flag.
__global__ void zero_kernel(float4* __restrict__ out4, int n4) {
    int i = blockIdx.x * blockDim.x + threadIdx.x;
    if (i < n4) out4[i] = make_float4(0.f, 0.f, 0.f, 0.f);
    if (i == 0) g_unmatched = 0;
}

// Launch 2: build 2-bit + byte tables; flag any unmatched node.
__global__ void build_kernel(const float* __restrict__ feat,
                             const float* __restrict__ ftu,
                             int V, int nwords2, int build2)
{
    int i = blockIdx.x * blockDim.x + threadIdx.x;
    if (build2 && i < nwords2) {
        unsigned int w = 0;
        int bad = 0;
        #pragma unroll 4
        for (int j = 0; j < 16; j++) {
            int v = i * 16 + j;
            int t = 0, found = 0;
            if (v < V) {
                float fv = feat[v];
                #pragma unroll
                for (int k = 0; k < T_TYPES; k++)
                    if (fv == ftu[k]) { t = k; found = 1; }
                if (!found) bad = 1;
                g_type[v] = found ? (signed char)t : (signed char)-1;
            }
            w |= ((unsigned int)t) << (2 * j);
        }
        g_pack2[i] = w;
        if (bad) atomicOr(&g_unmatched, 1);
    } else if (!build2 && i < V) {
        float fv = feat[i];
        signed char t = -1;
        #pragma unroll
        for (int k = 0; k < T_TYPES; k++)
            if (fv == ftu[k]) t = (signed char)k;
        g_type[i] = t;
    }
}

// Launch 3 (fast path): persistent blocks, 2-bit type table in 25KB smem,
// quad-cooperative compute, exp2-folded cutoff, quad-coalesced red.v4.
__global__ void __launch_bounds__(BLK, 6) edge_kernel_smem(
    const float* __restrict__ dist,
    const int*   __restrict__ src,
    const int*   __restrict__ dst,
    const float* __restrict__ cutoffs,
    const float* __restrict__ means,
    const float* __restrict__ scaling,
    float*       __restrict__ out,
    int E, int nwords2, int per_blk)
{
    extern __shared__ unsigned int s_pack[];
    __shared__ int s_unicos, s_fb;

    int tid  = threadIdx.x;
    int warp = tid >> 5;
    int lane = tid & 31;
    int c    = lane & 3;

    for (int i = tid; i < nwords2; i += BLK) s_pack[i] = g_pack2[i];
    if (tid == 0) {
        int u = 1;
        #pragma unroll
        for (int k = 1; k < K_F; k++) u &= (cutoffs[k] == cutoffs[0]);
        s_unicos = u;
        s_fb = g_unmatched;
    }

    // Per-lane radial params for this lane's 4 k's (hot path only needs m, ns2).
    float m[4], ns2[4];
    #pragma unroll
    for (int k = 0; k < 4; k++) {
        m[k]   = __ldg(&means[4 * c + k]);
        ns2[k] = -__ldg(&scaling[4 * c + k]) * LOG2E_F;
    }
    float cu0   = __ldg(&cutoffs[0]);
    float picu0 = PI_F / cu0;

    __syncthreads();
    int unicos = s_unicos;
    int fb     = s_fb;
    int qbase  = lane & ~3;

    int start = blockIdx.x * per_blk;
    int end   = start + per_blk;
    if (end > E) end = E;

    for (int base = start; base < end; base += BLK * 2) {
        int wb = base + warp * 64;
        int e  = wb + 2 * lane;              // even: float2/int2 aligned

        float d0 = 0.f, d1 = 0.f;
        int s0 = 0, s1 = 0, dd0 = 0, dd1 = 0;
        bool ok0 = (e < end), ok1 = (e + 1 < end);
        if (ok1) {
            float2 dv = *(const float2*)(dist + e);
            int2 sv   = *(const int2*)(src + e);
            int2 ddv  = *(const int2*)(dst + e);
            d0 = dv.x; d1 = dv.y;
            s0 = sv.x; s1 = sv.y;
            dd0 = ddv.x; dd1 = ddv.y;
        } else if (ok0) {
            d0 = dist[e]; s0 = src[e]; dd0 = dst[e];
        }

        int code0 = -1, code1 = -1;
        if (!fb) {
            // 2-bit table: every node has a valid type.
            if (ok0) code0 = dd0 * T_TYPES
                           + (int)((s_pack[s0 >> 4] >> ((s0 & 15) << 1)) & 3);
            if (ok1) code1 = dd1 * T_TYPES
                           + (int)((s_pack[s1 >> 4] >> ((s1 & 15) << 1)) & 3);
        } else {
            if (ok0) { int t = g_type[s0]; if (t >= 0) code0 = dd0 * T_TYPES + t; }
            if (ok1) { int t = g_type[s1]; if (t >= 0) code1 = dd1 * T_TYPES + t; }
        }

        // Uniform-cutoff: log2 of the cosine window, folded into exp2 arg.
        float lcv0 = 0.f, lcv1 = 0.f;
        if (unicos) {
            float cv0 = (d0 <= cu0) ? 0.5f * (__cosf(picu0 * d0) + 1.0f) : 0.0f;
            float cv1 = (d1 <= cu0) ? 0.5f * (__cosf(picu0 * d1) + 1.0f) : 0.0f;
            lcv0 = __log2f(cv0);     // cv=0 -> -inf -> exp2 -> 0
            lcv1 = __log2f(cv1);
        }

        #pragma unroll
        for (int pass = 0; pass < 2; pass++) {
            float dp = pass ? d1 : d0;
            float lp = pass ? lcv1 : lcv0;
            int   cp = pass ? code1 : code0;

            #pragma unroll
            for (int i = 0; i < 4; i++) {
                int srcl = qbase | i;
                float di = __shfl_sync(0xffffffffu, dp, srcl);
                int   ci = __shfl_sync(0xffffffffu, cp, srcl);

                float v0, v1, v2, v3;
                if (unicos) {
                    float li = __shfl_sync(0xffffffffu, lp, srcl);
                    float dm0 = di - m[0], dm1 = di - m[1];
                    float dm2 = di - m[2], dm3 = di - m[3];
                    v0 = exp2f(fmaf(ns2[0] * dm0, dm0, li));
                    v1 = exp2f(fmaf(ns2[1] * dm1, dm1, li));
                    v2 = exp2f(fmaf(ns2[2] * dm2, dm2, li));
                    v3 = exp2f(fmaf(ns2[3] * dm3, dm3, li));
                } else {
                    // Cold generic path: per-k cutoffs from global (cached).
                    float v[4];
                    #pragma unroll
                    for (int k = 0; k < 4; k++) {
                        float cu = __ldg(&cutoffs[4 * c + k]);
                        float cv = (di <= cu)
                                 ? 0.5f * (__cosf(PI_F * di / cu) + 1.0f) : 0.0f;
                        float dm = di - m[k];
                        v[k] = cv * exp2f(ns2[k] * dm * dm);
                    }
                    v0 = v[0]; v1 = v[1]; v2 = v[2]; v3 = v[3];
                }

                if (ci >= 0) {
                    // Quad's 4 lanes: one contiguous 64B-aligned region.
                    float* addr = out + ((size_t)ci << 4) + (c << 2);
                    asm volatile(
                        "red.global.add.v4.f32 [%0], {%1, %2, %3, %4};"
                        :: "l"(addr), "f"(v0), "f"(v1), "f"(v2), "f"(v3)
                        : "memory");
                }
            }
        }
    }
}

// Fallback (V too large for smem table): R11-style quad-cooperative kernel.
__global__ void __launch_bounds__(BLK) edge_kernel_fb(
    const float* __restrict__ feat,
    const float* __restrict__ dist,
    const int*   __restrict__ src,
    const int*   __restrict__ dst,
    const float* __restrict__ cutoffs,
    const float* __restrict__ means,
    const float* __restrict__ scaling,
    const float* __restrict__ ftu,
    float*       __restrict__ out,
    int E, int use_table)
{
    __shared__ float s_ftu[T_TYPES];
    __shared__ int s_unicos;

    int tid  = threadIdx.x;
    int warp = tid >> 5;
    int lane = tid & 31;
    int c    = lane & 3;

    if (tid < T_TYPES) s_ftu[tid] = ftu[tid];
    if (tid == 0) {
        int u = 1;
        #pragma unroll
        for (int k = 1; k < K_F; k++) u &= (cutoffs[k] == cutoffs[0]);
        s_unicos = u;
    }

    float m[4], ns2[4];
    #pragma unroll
    for (int k = 0; k < 4; k++) {
        m[k]   = __ldg(&means[4 * c + k]);
        ns2[k] = -__ldg(&scaling[4 * c + k]) * LOG2E_F;
    }
    float cu0   = __ldg(&cutoffs[0]);
    float picu0 = PI_F / cu0;

    __syncthreads();
    int unicos = s_unicos;
    int qbase = lane & ~3;

    int wb = (blockIdx.x * (BLK / 32) + warp) * 64;
    int e  = wb + 2 * lane;

    float d0 = 0.f, d1 = 0.f;
    int s0 = 0, s1 = 0, dd0 = 0, dd1 = 0;
    bool ok0 = (e < E), ok1 = (e + 1 < E);
    if (ok1) {
        float2 dv = *(const float2*)(dist + e);
        int2 sv   = *(const int2*)(src + e);
        int2 ddv  = *(const int2*)(dst + e);
        d0 = dv.x; d1 = dv.y; s0 = sv.x; s1 = sv.y; dd0 = ddv.x; dd1 = ddv.y;
    } else if (ok0) {
        d0 = dist[e]; s0 = src[e]; dd0 = dst[e];
    }

    int ty0 = -1, ty1 = -1;
    if (use_table) {
        if (ok0) ty0 = g_type[s0];
        if (ok1) ty1 = g_type[s1];
    } else {
        float fv0 = ok0 ? __ldg(&feat[s0]) : -1.f;
        float fv1 = ok1 ? __ldg(&feat[s1]) : -1.f;
        #pragma unroll
        for (int j = 0; j < T_TYPES; j++) {
            if (ok0 && fv0 == s_ftu[j]) ty0 = j;
            if (ok1 && fv1 == s_ftu[j]) ty1 = j;
        }
    }
    int code0 = (ty0 >= 0) ? (dd0 * T_TYPES + ty0) : -1;
    int code1 = (ty1 >= 0) ? (dd1 * T_TYPES + ty1) : -1;

    float lcv0 = 0.f, lcv1 = 0.f;
    if (unicos) {
        float cv0 = (d0 <= cu0) ? 0.5f * (__cosf(picu0 * d0) + 1.0f) : 0.0f;
        float cv1 = (d1 <= cu0) ? 0.5f * (__cosf(picu0 * d1) + 1.0f) : 0.0f;
        lcv0 = __log2f(cv0);
        lcv1 = __log2f(cv1);
    }

    #pragma unroll
    for (int pass = 0; pass < 2; pass++) {
        float dp = pass ? d1 : d0;
        float lp = pass ? lcv1 : lcv0;
        int   cp = pass ? code1 : code0;

        #pragma unroll
        for (int i = 0; i < 4; i++) {
            int srcl = qbase | i;
            float di = __shfl_sync(0xffffffffu, dp, srcl);
            int   ci = __shfl_sync(0xffffffffu, cp, srcl);

            float v0, v1, v2, v3;
            if (unicos) {
                float li = __shfl_sync(0xffffffffu, lp, srcl);
                float dm0 = di - m[0], dm1 = di - m[1];
                float dm2 = di - m[2], dm3 = di - m[3];
                v0 = exp2f(fmaf(ns2[0] * dm0, dm0, li));
                v1 = exp2f(fmaf(ns2[1] * dm1, dm1, li));
                v2 = exp2f(fmaf(ns2[2] * dm2, dm2, li));
                v3 = exp2f(fmaf(ns2[3] * dm3, dm3, li));
            } else {
                float v[4];
                #pragma unroll
                for (int k = 0; k < 4; k++) {
                    float cu = __ldg(&cutoffs[4 * c + k]);
                    float cv = (di <= cu)
                             ? 0.5f * (__cosf(PI_F * di / cu) + 1.0f) : 0.0f;
                    float dm = di - m[k];
                    v[k] = cv * exp2f(ns2[k] * dm * dm);
                }
                v0 = v[0]; v1 = v[1]; v2 = v[2]; v3 = v[3];
            }

            if (ci >= 0) {
                float* addr = out + ((size_t)ci << 4) + (c << 2);
                asm volatile(
                    "red.global.add.v4.f32 [%0], {%1, %2, %3, %4};"
                    :: "l"(addr), "f"(v0), "f"(v1), "f"(v2), "f"(v3)
                    : "memory");
            }
        }
    }
}

extern "C" void kernel_launch(void* const* d_in, const int* in_sizes, int n_in,
                              void* d_out, int out_size)
{
    const float* feat    = (const float*)d_in[0];
    const float* dist    = (const float*)d_in[1];
    const int*   src     = (const int*)  d_in[2];
    const int*   dst     = (const int*)  d_in[3];
    const float* cutoffs = (const float*)d_in[4];
    const float* means   = (const float*)d_in[5];
    const float* scaling = (const float*)d_in[6];
    const float* ftu     = (const float*)d_in[7];
    float* out = (float*)d_out;

    int E = in_sizes[2];
    int V = in_sizes[0];
    int nwords2 = (V + 15) / 16;

    int smem_ok = (nwords2 <= PACK2_CAP_WORDS) && (V <= TYPE_CAP);

    int n4 = out_size / 4;
    zero_kernel<<<(n4 + 255) / 256, 256>>>((float4*)out, n4);

    int bt = smem_ok ? nwords2 : V;
    build_kernel<<<(bt + 255) / 256, 256>>>(feat, ftu, V, nwords2, smem_ok);

    if (smem_ok) {
        size_t smem = (size_t)nwords2 * sizeof(unsigned int);
        cudaFuncSetAttribute(edge_kernel_smem,
                             cudaFuncAttributeMaxDynamicSharedMemorySize,
                             (int)smem);
        // persistent grid, per-block chunk in 64-edge (warp) granularity
        long long chunks = ((long long)E + 63) / 64;
        long long cpb = (chunks + NBLK_TARGET - 1) / NBLK_TARGET;
        int per_blk = (int)(cpb * 64);
        int nblk = (int)((E + per_blk - 1) / per_blk);
        edge_kernel_smem<<<nblk, BLK, smem>>>(
            dist, src, dst, cutoffs, means, scaling, out, E, nwords2, per_blk);
    } else {
        int use_table = (V <= TYPE_CAP) ? 1 : 0;
        int blocks = (E + 511) / 512;
        edge_kernel_fb<<<blocks, BLK>>>(
            feat, dist, src, dst, cutoffs, means, scaling, ftu, out,
            E, use_table);
    }
}